// round 16
// baseline (speedup 1.0000x reference)
#include <cuda_runtime.h>
#include <cuda_fp16.h>
#include <cstdint>

#define VV 8000
#define DD 128
#define UU 256
#define BB 32
#define SS 256
#define H3 768
#define H6 1536
#define MR 8192   // B*S
#define KC 1600   // WfT split-K chunk (x5)
#define NSPLIT 5

// ---------------- scratch (static device allocations; no cudaMalloc) ---------
__device__ __align__(128) __half g_w1h[2 * UU * VV];    // fp16(W1) [512,8000]
__device__ __align__(128) __half g_w2t[VV * VV];        // fp16(W2^T) [8000,8000]
__device__ __align__(128) __half g_embh[VV * DD];       // fp16(emb)
__device__ __align__(128) __half g_wcatt[H6 * DD];      // fp16([W_f|W_b]^T)
__device__ __align__(128) float  g_bcat[H6];
__device__ __align__(128) float  g_embw[VV * H6];       // emb proj + bias (fp32)
__device__ __align__(128) __half g_hcat[MR * 2 * UU];   // fp16 GRU outputs
__device__ __align__(128) __half g_wfth[VV * 2 * UU];   // fp16((W1@W2)^T) [8000,512]
__device__ __align__(128) float  g_partk[NSPLIT * VV * 2 * UU];  // split-K partials
__device__ __align__(128) float  g_bf[VV];
__device__ __align__(128) float  g_zb[2 * UU];          // zero bias (never written)
__device__ __align__(128) float  g_uperm[2 * 4 * UU * 192];
__device__ int g_cnt[128];                               // per-tile split counters

// ---------------- side stream + events (created at static init) ---------------
struct StreamInit {
    cudaStream_t s1;
    cudaEvent_t ev0, ev2;
    StreamInit() {
        cudaStreamCreateWithFlags(&s1, cudaStreamNonBlocking);
        cudaEventCreateWithFlags(&ev0, cudaEventDisableTiming);
        cudaEventCreateWithFlags(&ev2, cudaEventDisableTiming);
    }
};
static StreamInit g_si;

// packed f32x2 helpers (sm_103a)
__device__ __forceinline__ unsigned long long pack2(float x, float y) {
    unsigned long long r;
    asm("mov.b64 %0, {%1,%2};" : "=l"(r) : "f"(x), "f"(y));
    return r;
}
__device__ __forceinline__ float2 unpack2(unsigned long long v) {
    float2 r;
    asm("mov.b64 {%0,%1}, %2;" : "=f"(r.x), "=f"(r.y) : "l"(v));
    return r;
}
#define FMA2(acc, a, b) \
    asm("fma.rn.f32x2 %0, %1, %2, %0;" : "+l"(acc) : "l"(a), "l"(b))

// DSMEM / cluster helpers
__device__ __forceinline__ uint32_t mapa_u32(uint32_t laddr, uint32_t rank) {
    uint32_t r;
    asm("mapa.shared::cluster.u32 %0, %1, %2;" : "=r"(r) : "r"(laddr), "r"(rank));
    return r;
}
#define CLUSTER_ARRIVE() asm volatile("barrier.cluster.arrive.aligned;" ::: "memory")
#define CLUSTER_WAIT()   asm volatile("barrier.cluster.wait.aligned;" ::: "memory")

// async remote store with mbarrier tx completion (sm_90+)
#define ST_ASYNC_U64(raddr, v, rmbar) \
    asm volatile("st.async.shared::cluster.mbarrier::complete_tx::bytes.u64 [%0], %1, [%2];" \
                 :: "r"(raddr), "l"(v), "r"(rmbar) : "memory")

#define MBARRIER_INIT(addr, cnt) \
    asm volatile("mbarrier.init.shared.b64 [%0], %1;" :: "r"((uint32_t)(addr)), "r"((uint32_t)(cnt)) : "memory")
#define MBARRIER_EXPECT_TX(addr, tx) \
    asm volatile("mbarrier.arrive.expect_tx.shared.b64 _, [%0], %1;" \
                 :: "r"((uint32_t)(addr)), "r"((uint32_t)(tx)) : "memory")
#define MBARRIER_WAIT_PARITY(addr, par) do {                                   \
    uint32_t _m = (uint32_t)(addr); uint32_t _p = (uint32_t)(par);             \
    asm volatile(                                                              \
        "{\n\t.reg .pred P1;\n\t"                                              \
        "WL_%=:\n\t"                                                           \
        "mbarrier.try_wait.parity.acquire.cta.shared::cta.b64 P1, [%0], %1, 0x989680;\n\t" \
        "@P1 bra.uni WD_%=;\n\t"                                               \
        "bra.uni WL_%=;\n\t"                                                   \
        "WD_%=:\n\t}"                                                          \
        :: "r"(_m), "r"(_p) : "memory");                                       \
} while (0)

// ---------------- prep_main: embh + wcatt/bcat + uperm (GRU-side inputs) ------
#define P_EMB  (VV * DD / 4)
#define P_WCAT (H6 * DD)
#define P_U    (2 * 4 * UU * 192)
#define PM_TOT (P_EMB + P_WCAT + P_U)

__global__ void __launch_bounds__(256) prep_main(
    const float* __restrict__ emb, __half* __restrict__ embh,
    const float* __restrict__ Wf_, const float* __restrict__ Wb_,
    const float* __restrict__ bfb, const float* __restrict__ bbb,
    __half* __restrict__ wcatt, float* __restrict__ bcat,
    const float* __restrict__ Uf, const float* __restrict__ Ub,
    float* __restrict__ uperm)
{
    int i = blockIdx.x * 256 + threadIdx.x;
    if (i < P_EMB) {
        float4 v = ((const float4*)emb)[i];
        __half2 h0 = __floats2half2_rn(v.x, v.y);
        __half2 h1 = __floats2half2_rn(v.z, v.w);
        uint2 r;
        r.x = *reinterpret_cast<uint32_t*>(&h0);
        r.y = *reinterpret_cast<uint32_t*>(&h1);
        ((uint2*)embh)[i] = r;
        return;
    }
    i -= P_EMB;
    if (i < P_WCAT) {
        int n = i / DD, k = i % DD;
        float v = (n < H3) ? Wf_[k * H3 + n] : Wb_[k * H3 + (n - H3)];
        wcatt[i] = __float2half_rn(v);
        if (i < H6)
            bcat[i] = (i < H3) ? bfb[i] : bbb[i - H3];
        return;
    }
    i -= P_WCAT;
    if (i < P_U) {
        int c = i % 192;
        int k = (i / 192) % UU;
        int r = (i / (192 * UU)) % 4;
        int dir = i / (192 * UU * 4);
        const float* Um = dir ? Ub : Uf;
        int col = (c < 64) ? (64 * r + c)
                : (c < 128) ? (UU + 64 * r + (c - 64))
                            : (2 * UU + 64 * r + (c - 128));
        uperm[i] = Um[k * H3 + col];
    }
}

// ---------------- prep_side: W2 transpose (fp16) + W1 cvt + counter zero ------
#define P_W1   (2 * UU * VV / 4)
#define TR_BLK (VV / 32 * VV / 32)     // 62500
#define W1_BLK ((P_W1 + 255) / 256)    // 4000
#define PS_GRID (TR_BLK + W1_BLK)

__global__ void __launch_bounds__(256) prep_side(
    const float* __restrict__ W2, __half* __restrict__ w2t,
    const float* __restrict__ W1, __half* __restrict__ w1h,
    int* __restrict__ cnt)
{
    __shared__ float t[32][33];
    int b = blockIdx.x;
    int tid = threadIdx.x;
    if (b < TR_BLK) {
        int bx = (b % (VV / 32)) * 32;
        int by = (b / (VV / 32)) * 32;
        int x = tid & 31, y0 = tid >> 5;
#pragma unroll
        for (int dy = 0; dy < 32; dy += 8)
            t[y0 + dy][x] = W2[(size_t)(by + y0 + dy) * VV + bx + x];
        __syncthreads();
#pragma unroll
        for (int dy = 0; dy < 32; dy += 8)
            w2t[(size_t)(bx + y0 + dy) * VV + by + x] = __float2half_rn(t[x][y0 + dy]);
        return;
    }
    if (b == TR_BLK && tid < 128) cnt[tid] = 0;
    int i = (b - TR_BLK) * 256 + tid;
    if (i < P_W1) {
        float4 v = ((const float4*)W1)[i];
        __half2 h0 = __floats2half2_rn(v.x, v.y);
        __half2 h1 = __floats2half2_rn(v.z, v.w);
        uint2 r;
        r.x = *reinterpret_cast<uint32_t*>(&h0);
        r.y = *reinterpret_cast<uint32_t*>(&h1);
        ((uint2*)w1h)[i] = r;
    }
}

// ---------------- fp16 GEMM body (mma.sync m16n8k16, fp32 accum) --------------
#define HBM_ 128
#define HBN_ 256
#define HBK_ 32
#define HNST 4
#define HROWB 80
#define HASB (HBM_ * HROWB)
#define HBSB (HBN_ * HROWB)
#define HSTG (HASB + HBSB)
#define HGE_SMEM (HNST * HSTG)

__device__ __forceinline__ void gemm_body(
    const __half* __restrict__ A, int lda,
    const __half* __restrict__ Bt, int ldb,
    const float* __restrict__ bias, float* __restrict__ C,
    int M, int N, int K, int tile, unsigned char* sm)
{
    int ntiles = (N + HBN_ - 1) / HBN_;
    int mt = tile / ntiles, nt = tile % ntiles;
    int m0 = mt * HBM_, n0 = nt * HBN_;

    int tid = threadIdx.x;
    int lane = tid & 31;
    int wid = tid >> 5;
    int wm = wid >> 2;
    int wn = wid & 3;
    int g = lane >> 2;
    int t4 = lane & 3;

    uint32_t sbase = (uint32_t)__cvta_generic_to_shared(sm);

    float acc[4][8][4];
#pragma unroll
    for (int a = 0; a < 4; a++)
#pragma unroll
        for (int b = 0; b < 8; b++)
#pragma unroll
            for (int c = 0; c < 4; c++) acc[a][b][c] = 0.f;

    const int KT = K / HBK_;

    auto issue = [&](int kt, int slot) {
        int k0 = kt * HBK_;
        uint32_t ab = sbase + slot * HSTG;
        uint32_t bb = ab + HASB;
#pragma unroll
        for (int i = 0; i < 2; i++) {
            int ch = tid + i * 256;
            int r = ch >> 2, c16 = ch & 3;
            int ra = m0 + r; if (ra >= M) ra = M - 1;
            const __half* src = A + (size_t)ra * lda + k0 + c16 * 8;
            uint32_t dst = ab + (uint32_t)(r * HROWB + c16 * 16);
            asm volatile("cp.async.cg.shared.global [%0],[%1],16;\n" :: "r"(dst), "l"(src));
        }
#pragma unroll
        for (int i = 0; i < 4; i++) {
            int ch = tid + i * 256;
            int r = ch >> 2, c16 = ch & 3;
            int nb = n0 + r;
            int sz = (nb < N) ? 16 : 0;
            if (nb >= N) nb = N - 1;
            const __half* src = Bt + (size_t)nb * ldb + k0 + c16 * 8;
            uint32_t dst = bb + (uint32_t)(r * HROWB + c16 * 16);
            asm volatile("cp.async.cg.shared.global [%0],[%1],16,%2;\n" :: "r"(dst), "l"(src), "r"(sz));
        }
        asm volatile("cp.async.commit_group;\n");
    };

    auto docompute = [&](int slot) {
        const unsigned char* As = sm + slot * HSTG;
        const unsigned char* Bs = As + HASB;
#pragma unroll
        for (int kk = 0; kk < 2; kk++) {
            int kb = kk * 32 + t4 * 4;
            uint32_t af[4][4];
#pragma unroll
            for (int mi = 0; mi < 4; mi++) {
                int row = wm * 64 + mi * 16 + g;
                const unsigned char* p = As + row * HROWB + kb;
                af[mi][0] = *(const uint32_t*)(p);
                af[mi][1] = *(const uint32_t*)(p + 8 * HROWB);
                af[mi][2] = *(const uint32_t*)(p + 16);
                af[mi][3] = *(const uint32_t*)(p + 8 * HROWB + 16);
            }
            uint32_t bf[8][2];
#pragma unroll
            for (int ni = 0; ni < 8; ni++) {
                int nr = wn * 64 + ni * 8 + g;
                const unsigned char* p = Bs + nr * HROWB + kb;
                bf[ni][0] = *(const uint32_t*)(p);
                bf[ni][1] = *(const uint32_t*)(p + 16);
            }
#pragma unroll
            for (int mi = 0; mi < 4; mi++)
#pragma unroll
                for (int ni = 0; ni < 8; ni++) {
                    asm volatile(
                        "mma.sync.aligned.m16n8k16.row.col.f32.f16.f16.f32 "
                        "{%0,%1,%2,%3},{%4,%5,%6,%7},{%8,%9},{%0,%1,%2,%3};\n"
                        : "+f"(acc[mi][ni][0]), "+f"(acc[mi][ni][1]),
                          "+f"(acc[mi][ni][2]), "+f"(acc[mi][ni][3])
                        : "r"(af[mi][0]), "r"(af[mi][1]), "r"(af[mi][2]), "r"(af[mi][3]),
                          "r"(bf[ni][0]), "r"(bf[ni][1]));
                }
        }
    };

    issue(0, 0);
    if (KT > 1) issue(1, 1);
    if (KT > 2) issue(2, 2);

#pragma unroll 1
    for (int kt = 0; kt < KT; kt++) {
        if (kt + 1 < KT) {
            asm volatile("cp.async.wait_group %0;\n" :: "n"(HNST - 2));
        } else {
            asm volatile("cp.async.wait_group 0;\n");
        }
        __syncthreads();
        if (kt + HNST - 1 < KT)
            issue(kt + HNST - 1, (kt + HNST - 1) & (HNST - 1));
        docompute(kt & (HNST - 1));
    }

#pragma unroll
    for (int ni = 0; ni < 8; ni++) {
        int c = n0 + wn * 64 + ni * 8 + t4 * 2;
        if (c >= N) continue;
        float b0v = bias[c], b1v = bias[c + 1];
#pragma unroll
        for (int mi = 0; mi < 4; mi++) {
            int r = m0 + wm * 64 + mi * 16 + g;
            if (r >= M) continue;
            *reinterpret_cast<float2*>(&C[(size_t)r * N + c]) =
                make_float2(acc[mi][ni][0] + b0v, acc[mi][ni][1] + b1v);
            if (r + 8 < M)
                *reinterpret_cast<float2*>(&C[(size_t)(r + 8) * N + c]) =
                    make_float2(acc[mi][ni][2] + b0v, acc[mi][ni][3] + b1v);
        }
    }
}

// standalone GEMM (embW projection + final logits)
__global__ void __launch_bounds__(256) gemm_h0(
    const __half* __restrict__ A, int lda, const __half* __restrict__ Bt, int ldb,
    const float* __restrict__ bias, float* __restrict__ C,
    int M, int N, int K)
{
    extern __shared__ __align__(16) unsigned char sm[];
    gemm_body(A, lda, Bt, ldb, bias, C, M, N, K, blockIdx.x, sm);
}

// ---------------- megaW: WfT split-K GEMM + inline last-block reduce + bias ---
#define NTILE_W 126              // 63 m-tiles x 2 n-tiles
#define NWFT  (NSPLIT * NTILE_W) // 630
#define NBIAS (VV / 8)           // 1000
#define MW_GRID (NWFT + NBIAS)

__global__ void __launch_bounds__(256) megaW(
    const __half* __restrict__ w2t, const __half* __restrict__ w1h,
    float* __restrict__ partk, const float* __restrict__ zb,
    __half* __restrict__ wfth, int* __restrict__ cnt,
    const float* __restrict__ b1, const float* __restrict__ b2,
    float* __restrict__ bf)
{
    extern __shared__ __align__(16) unsigned char sm[];
    __shared__ int oldc;
    int b = blockIdx.x;
    if (b < NWFT) {
        int t = b / NSPLIT, kz = b % NSPLIT;
        gemm_body(w2t + (size_t)kz * KC, VV,
                  w1h + (size_t)kz * KC, VV,
                  zb, partk + (size_t)kz * VV * 2 * UU,
                  VV, 2 * UU, KC, t, sm);
        // publish partials, count; last of 5 reduces this tile
        __threadfence();
        __syncthreads();
        if (threadIdx.x == 0) {
            int ret;
            asm volatile("atom.acq_rel.gpu.global.add.s32 %0, [%1], 1;"
                         : "=r"(ret) : "l"(cnt + t) : "memory");
            oldc = ret;
        }
        __syncthreads();
        if (oldc == NSPLIT - 1) {
            __threadfence();
            int mt = t / 2, nt = t % 2;
            int r0 = mt * HBM_, c0 = nt * HBN_;
            for (int e = threadIdx.x; e < HBM_ * (HBN_ / 4); e += 256) {
                int rr = r0 + e / (HBN_ / 4);
                int cc = c0 + (e % (HBN_ / 4)) * 4;
                if (rr >= VV) continue;
                size_t off = (size_t)rr * (2 * UU) + cc;
                float4 s = *(const float4*)(partk + off);
#pragma unroll
                for (int z = 1; z < NSPLIT; z++) {
                    float4 v = *(const float4*)(partk + (size_t)z * VV * 2 * UU + off);
                    s.x += v.x; s.y += v.y; s.z += v.z; s.w += v.w;
                }
                __half2 h0 = __floats2half2_rn(s.x, s.y);
                __half2 h1 = __floats2half2_rn(s.z, s.w);
                uint2 r;
                r.x = *reinterpret_cast<uint32_t*>(&h0);
                r.y = *reinterpret_cast<uint32_t*>(&h1);
                *(uint2*)(wfth + off) = r;
            }
        }
    } else {
        int nb = b - NWFT;
        int n = nb * 8 + (threadIdx.x >> 5);
        int lane = threadIdx.x & 31;
        const __half2* row = (const __half2*)(w2t + (size_t)n * VV);
        const float2* b1p = (const float2*)b1;
        float acc = 0.f;
#pragma unroll 5
        for (int i = 0; i < VV / 64; i++) {
            int idx = i * 32 + lane;
            float2 f = __half22float2(row[idx]);
            float2 bb = b1p[idx];
            acc += bb.x * f.x + bb.y * f.y;
        }
#pragma unroll
        for (int off = 16; off > 0; off >>= 1)
            acc += __shfl_xor_sync(0xFFFFFFFF, acc, off);
        if (lane == 0) bf[n] = acc + b2[n];
    }
}

// ---------------- GRU: 384 threads, 8-way k-split, st.async sync (R13) --------
#define GRU_THREADS 384
#define GRU_SM_US   (UU * 192 * 4)              // 196608
#define GRU_SM_PART (16 * 192 * 4)              // 12288
#define GRU_SM_H    (2 * 2 * UU * 8)            // 8192
#define GRU_SMEM    (GRU_SM_US + GRU_SM_PART + GRU_SM_H + 16)
#define UREG 20

__global__ void __launch_bounds__(GRU_THREADS, 1) __cluster_dims__(4, 1, 1)
gru_scan(const float* __restrict__ embW, const float* __restrict__ uperm,
         const float* __restrict__ bf1, const float* __restrict__ bb1,
         const int* __restrict__ tokens, __half* __restrict__ hcat)
{
    extern __shared__ __align__(16) unsigned char smraw[];
    float* Us   = (float*)smraw;
    float* part = (float*)(smraw + GRU_SM_US);
    unsigned long long* hbuf =
        (unsigned long long*)(smraw + GRU_SM_US + GRU_SM_PART);
    uint32_t mb0 = (uint32_t)__cvta_generic_to_shared(smraw + GRU_SM_US + GRU_SM_PART + GRU_SM_H);

    int tid  = threadIdx.x;
    int cid  = blockIdx.x >> 2;
    int rank = blockIdx.x & 3;
    int bp   = cid & 15;
    int dir  = cid >> 4;
    int b0   = bp * 2;
    const float* bv = dir ? bb1 : bf1;

    {
        const float4* src = (const float4*)(uperm + (size_t)(dir * 4 + rank) * UU * 192);
        float4* dst = (float4*)Us;
        for (int i = tid; i < UU * 192 / 4; i += GRU_THREADS) dst[i] = src[i];
        for (int i = tid; i < 2 * 2 * UU; i += GRU_THREADS) hbuf[i] = 0ull;
    }
    if (tid == 0) { MBARRIER_INIT(mb0, 1); MBARRIER_INIT(mb0 + 8, 1); }
    __syncthreads();
    CLUSTER_ARRIVE();
    CLUSTER_WAIT();

    int kc = tid / 48;     // 0..7: k-range of 32
    int ct = tid % 48;     // 2 col-pairs (4 cols)
    int k0 = kc * 32;

    const ulonglong2* U2 = (const ulonglong2*)Us;
    ulonglong2 ur[UREG];
#pragma unroll
    for (int kk = 0; kk < UREG; kk++)
        ur[kk] = U2[(size_t)(k0 + kk) * 48 + ct];

    int jj = tid & 63;
    int ub = (tid >> 6) & 1;
    int j  = rank * 64 + jj;
    float bz = 0.f, br = 0.f, bh = 0.f;
    if (tid < 128) { bz = bv[j]; br = bv[UU + j]; bh = bv[2 * UU + j]; }

    uint32_t hl = (uint32_t)__cvta_generic_to_shared(hbuf);
    uint32_t hpeer[4], mpeer[4];
#pragma unroll
    for (int r = 0; r < 4; r++) {
        hpeer[r] = mapa_u32(hl, r);
        mpeer[r] = mapa_u32(mb0, r);
    }

    int ph0 = 0, ph1 = 0;

    for (int i = 0; i < SS; i++) {
        int p = i & 1;
        if (tid == 0 && i < SS - 1)
            MBARRIER_EXPECT_TX(mb0 + (p ^ 1) * 8, 4096);

        float pz = 0.f, pr = 0.f, phx = 0.f; int tk = 1;
        size_t rb = 0;
        if (tid < 128) {
            int s = dir ? (SS - 1 - i) : i;
            rb = (size_t)(b0 + ub) * SS + s;
            tk = tokens[rb];
            const float* xr = embW + (size_t)tk * H6 + dir * H3;
            pz = xr[j]; pr = xr[UU + j]; phx = xr[2 * UU + j];
        }

        if (i > 0) {
            if (p == 0) { MBARRIER_WAIT_PARITY(mb0,     ph0); ph0 ^= 1; }
            else        { MBARRIER_WAIT_PARITY(mb0 + 8, ph1); ph1 ^= 1; }
        }

        {
            unsigned long long a00 = 0, a01 = 0, a10 = 0, a11 = 0;
            const ulonglong2* h0 = (const ulonglong2*)(hbuf + (p * 2 + 0) * UU) + kc * 16;
            const ulonglong2* h1 = (const ulonglong2*)(hbuf + (p * 2 + 1) * UU) + kc * 16;
#pragma unroll
            for (int kk = 0; kk < UREG / 2; kk++) {
                ulonglong2 uA = ur[2 * kk];
                ulonglong2 uB = ur[2 * kk + 1];
                ulonglong2 hA = h0[kk];
                ulonglong2 hB = h1[kk];
                FMA2(a00, uA.x, hA.x); FMA2(a01, uA.y, hA.x);
                FMA2(a10, uA.x, hB.x); FMA2(a11, uA.y, hB.x);
                FMA2(a00, uB.x, hA.y); FMA2(a01, uB.y, hA.y);
                FMA2(a10, uB.x, hB.y); FMA2(a11, uB.y, hB.y);
            }
            const ulonglong2* up = U2 + (size_t)(k0 + UREG) * 48 + ct;
#pragma unroll
            for (int kk = UREG / 2; kk < 16; kk++) {
                ulonglong2 uA = up[0];
                ulonglong2 uB = up[48];
                up += 96;
                ulonglong2 hA = h0[kk];
                ulonglong2 hB = h1[kk];
                FMA2(a00, uA.x, hA.x); FMA2(a01, uA.y, hA.x);
                FMA2(a10, uA.x, hB.x); FMA2(a11, uA.y, hB.x);
                FMA2(a00, uB.x, hA.y); FMA2(a01, uB.y, hA.y);
                FMA2(a10, uB.x, hB.y); FMA2(a11, uB.y, hB.y);
            }
            float2 p00 = unpack2(a00), p01 = unpack2(a01);
            float2 p10 = unpack2(a10), p11 = unpack2(a11);
            ((float4*)(part + (kc * 2 + 0) * 192))[ct] = make_float4(p00.x, p00.y, p01.x, p01.y);
            ((float4*)(part + (kc * 2 + 1) * 192))[ct] = make_float4(p10.x, p10.y, p11.x, p11.y);
        }
        __syncthreads();

        if (tid < 128) {
            float iz = 0.f, ir = 0.f, ih = 0.f;
#pragma unroll
            for (int q = 0; q < 8; q++) {
                const float* pr_ = part + (2 * q + ub) * 192;
                iz += pr_[jj];
                ir += pr_[64 + jj];
                ih += pr_[128 + jj];
            }

            float hold = ((const float*)&hbuf[(p * 2 + ub) * UU + j])[0];
            float z = 1.f / (1.f + __expf(-(pz + iz + bz)));
            float g = 1.f / (1.f + __expf(-(pr + ir + br)));
            float c = tanhf(phx + g * (ih + bh));
            float hn = z * hold + (1.f - z) * c;
            if (tk == 0) hn = hold;

            if (i < SS - 1) {
                unsigned long long hd = pack2(hn, hn);
                uint32_t off = (uint32_t)(((p ^ 1) * 2 + ub) * UU + j) * 8u;
                uint32_t mboff = (uint32_t)((p ^ 1) * 8);
#pragma unroll
                for (int r = 0; r < 4; r++)
                    ST_ASYNC_U64(hpeer[r] + off, hd, mpeer[r] + mboff);
            }
            hcat[rb * (2 * UU) + dir * UU + j] = __float2half_rn(hn);
        }
    }
    CLUSTER_ARRIVE();
    CLUSTER_WAIT();
}

// ---------------- host launcher ----------------------------------------------
extern "C" void kernel_launch(void* const* d_in, const int* in_sizes, int n_in,
                              void* d_out, int out_size)
{
    const int*   tokens = (const int*)d_in[0];
    const float* emb    = (const float*)d_in[1];
    const float* W_f    = (const float*)d_in[2];
    const float* U_f    = (const float*)d_in[3];
    const float* b_f    = (const float*)d_in[4];
    const float* W_b    = (const float*)d_in[5];
    const float* U_b    = (const float*)d_in[6];
    const float* b_b    = (const float*)d_in[7];
    const float* W1     = (const float*)d_in[8];
    const float* b1     = (const float*)d_in[9];
    const float* W2     = (const float*)d_in[10];
    const float* b2     = (const float*)d_in[11];
    float* out = (float*)d_out;

    __half *w1h, *w2t, *embh, *wcatt, *hcat, *wfth;
    float *bcat, *embw, *bfv, *uperm, *partk, *zb;
    int* cnt;
    cudaGetSymbolAddress((void**)&w1h,   g_w1h);
    cudaGetSymbolAddress((void**)&w2t,   g_w2t);
    cudaGetSymbolAddress((void**)&embh,  g_embh);
    cudaGetSymbolAddress((void**)&wcatt, g_wcatt);
    cudaGetSymbolAddress((void**)&bcat,  g_bcat);
    cudaGetSymbolAddress((void**)&embw,  g_embw);
    cudaGetSymbolAddress((void**)&hcat,  g_hcat);
    cudaGetSymbolAddress((void**)&wfth,  g_wfth);
    cudaGetSymbolAddress((void**)&bfv,   g_bf);
    cudaGetSymbolAddress((void**)&uperm, g_uperm);
    cudaGetSymbolAddress((void**)&partk, g_partk);
    cudaGetSymbolAddress((void**)&zb,    g_zb);
    cudaGetSymbolAddress((void**)&cnt,   g_cnt);

    cudaFuncSetAttribute(megaW,   cudaFuncAttributeMaxDynamicSharedMemorySize, HGE_SMEM);
    cudaFuncSetAttribute(gemm_h0, cudaFuncAttributeMaxDynamicSharedMemorySize, HGE_SMEM);
    cudaFuncSetAttribute(gru_scan, cudaFuncAttributeMaxDynamicSharedMemorySize, GRU_SMEM);

    // fork: side stream joins the capture via ev0
    cudaEventRecord(g_si.ev0, 0);
    cudaStreamWaitEvent(g_si.s1, g_si.ev0, 0);

    // main chain: small prep -> embW -> GRU
    prep_main<<<(PM_TOT + 255) / 256, 256>>>(emb, embh, W_f, W_b, b_f, b_b,
                                             wcatt, bcat, U_f, U_b, uperm);
    {
        int mtiles = (VV + HBM_ - 1) / HBM_;     // 63
        int ntiles = H6 / HBN_;                  // 6
        gemm_h0<<<mtiles * ntiles, 256, HGE_SMEM>>>(embh, DD, wcatt, DD,
                                                    bcat, embw, VV, H6, DD);
    }
    gru_scan<<<128, GRU_THREADS, GRU_SMEM>>>(embw, uperm, b_f + H3, b_b + H3,
                                             tokens, hcat);

    // side chain: W2 transpose + W1 cvt -> WfT split-K (inline reduce) + bias
    prep_side<<<PS_GRID, 256, 0, g_si.s1>>>(W2, w2t, W1, w1h, cnt);
    megaW<<<MW_GRID, 256, HGE_SMEM, g_si.s1>>>(w2t, w1h, partk, zb, wfth, cnt,
                                               b1, b2, bfv);
    cudaEventRecord(g_si.ev2, g_si.s1);

    // join: logits = hcat @ Wf + bf -> output
    cudaStreamWaitEvent(0, g_si.ev2, 0);
    {
        int mtiles = MR / HBM_;                  // 64
        int ntiles = (VV + HBN_ - 1) / HBN_;     // 32
        gemm_h0<<<mtiles * ntiles, 256, HGE_SMEM>>>(hcat, 2 * UU, wfth, 2 * UU,
                                                    bfv, out, MR, VV, 2 * UU);
    }
}